// round 7
// baseline (speedup 1.0000x reference)
#include <cuda_runtime.h>
#include <cuda_bf16.h>
#include <math.h>

// ---------------- problem constants ----------------
#define B_N   32
#define L_N   4096
#define C_N   96
#define GG_N  64
#define NW_N  2048
#define T_N   131072
#define HID_N 384

#define OUT0_ELEMS (T_N * C_N)
#define ATTN_ELEMS (NW_N * 3 * GG_N * GG_N)

#define SCALE_F 0.17677669529663687f  // 32^-0.5

// ---------------- scratch ----------------
__device__ float g_attn_fb[ATTN_ELEMS];  // fallback sink for attn probs

// precomputed bf16 weights, [n][k] layout, k padded to 100
__device__ __nv_bfloat16 g_wqkv_bf[288 * 100];
__device__ __nv_bfloat16 g_wproj_bf[96 * 100];
__device__ __nv_bfloat16 g_w1_bf[384 * 100];
__device__ __nv_bfloat16 g_w2_bf[4 * 96 * 100];  // [chunk][n][k]

#define QKV_E  (288 * 96)
#define PROJ_E (96 * 96)
#define W1_E   (384 * 96)
#define W2_E   (4 * 96 * 96)

__global__ void prep_weights(const float* __restrict__ wqkv,
                             const float* __restrict__ wproj,
                             const float* __restrict__ w1,
                             const float* __restrict__ w2) {
    int i = blockIdx.x * 256 + threadIdx.x;
    if (i < QKV_E) {
        int n = i / 96, k = i - n * 96;
        g_wqkv_bf[n * 100 + k] = __float2bfloat16(wqkv[(size_t)k * 288 + n]);
        return;
    }
    i -= QKV_E;
    if (i < PROJ_E) {
        int n = i / 96, k = i - n * 96;
        g_wproj_bf[n * 100 + k] = __float2bfloat16(wproj[(size_t)k * 96 + n]);
        return;
    }
    i -= PROJ_E;
    if (i < W1_E) {
        int n = i / 96, k = i - n * 96;
        g_w1_bf[n * 100 + k] = __float2bfloat16(w1[(size_t)k * 384 + n]);
        return;
    }
    i -= W1_E;
    if (i < W2_E) {
        int c = i / 9216, r = i - c * 9216;
        int n = r / 96, k = r - n * 96;
        g_w2_bf[c * 9600 + n * 100 + k] =
            __float2bfloat16(w2[(size_t)(c * 96 + k) * 96 + n]);
    }
}

__device__ __forceinline__ int win2tok(int m) {
    int w = m >> 6, t = m & 63;
    int b = w >> 6, rem = w & 63;
    int hy = rem >> 3, wx = rem & 7;
    int gy = t >> 3,  gx = t & 7;
    return b * L_N + (hy * 8 + gy) * 64 + (wx * 8 + gx);
}

__device__ __forceinline__ void mma16(float* c, const unsigned* a, const unsigned* b) {
    asm volatile(
        "mma.sync.aligned.m16n8k16.row.col.f32.bf16.bf16.f32 "
        "{%0,%1,%2,%3}, {%4,%5,%6,%7}, {%8,%9}, {%0,%1,%2,%3};\n"
        : "+f"(c[0]), "+f"(c[1]), "+f"(c[2]), "+f"(c[3])
        : "r"(a[0]), "r"(a[1]), "r"(a[2]), "r"(a[3]), "r"(b[0]), "r"(b[1]));
}

// ---------------- fused block kernel: whole transformer block per window ---
// smem layout (bytes):
#define SM_U    0        // 19200: weight stage (96x100 bf16) / Ss fp32 (64x66) / W1 chunk
#define SM_QS   19200    // 12800: Q (scaled); later W2 chunk (19200 spans QS+KS)
#define SM_KS   32000    // 12800: K
#define SM_VT   44800    // 13824: V^T, [c][t] bf16 stride 72
#define SM_PS   58624    // 12800: As (LN x) -> Ps (probs) -> As2 (LN2)
#define SM_OS   71424    // 12800: attn out + lepe -> Hs (gelu hidden)
#define SM_XS   84224    // 24576: x rows fp32 -> x1 rows fp32 (in place)
#define SM_MEGA 108800

__global__ __launch_bounds__(256, 2)
void block_kernel(const float* __restrict__ x,
                  const float* __restrict__ bqkv,
                  const float* __restrict__ wl,
                  const float* __restrict__ bl,
                  const float* __restrict__ bproj,
                  const float* __restrict__ g1,
                  const float* __restrict__ bt1,
                  const float* __restrict__ g2,
                  const float* __restrict__ bt2,
                  const float* __restrict__ b1,
                  const float* __restrict__ b2,
                  float* __restrict__ out,
                  float* __restrict__ attn_out) {
    extern __shared__ char smraw[];
    __nv_bfloat16* U   = (__nv_bfloat16*)(smraw + SM_U);
    float*         Ssm = (float*)(smraw + SM_U);
    __nv_bfloat16* Qs  = (__nv_bfloat16*)(smraw + SM_QS);
    __nv_bfloat16* W2s = (__nv_bfloat16*)(smraw + SM_QS);  // MLP phase
    __nv_bfloat16* Ks  = (__nv_bfloat16*)(smraw + SM_KS);
    __nv_bfloat16* Vt  = (__nv_bfloat16*)(smraw + SM_VT);
    __nv_bfloat16* As  = (__nv_bfloat16*)(smraw + SM_PS);  // LN1, then Ps, then LN2
    __nv_bfloat16* Ps  = (__nv_bfloat16*)(smraw + SM_PS);
    __nv_bfloat16* Os  = (__nv_bfloat16*)(smraw + SM_OS);  // attn-out, then Hs
    __nv_bfloat16* Hs  = (__nv_bfloat16*)(smraw + SM_OS);
    float*         Xs  = (float*)(smraw + SM_XS);

    int w = blockIdx.x;
    int tid = threadIdx.x, lane = tid & 31, wid = tid >> 5;
    int g = lane >> 2, tig = lane & 3;
    int mw = (wid >> 1) * 16;

    // ---- phase 0: load x window rows, LN1 -> As (bf16), x -> Xs (fp32) ----
    #pragma unroll
    for (int r = 0; r < 8; r++) {
        int t = wid * 8 + r;
        const float* xr = x + (size_t)win2tok(w * 64 + t) * 96;
        float v0 = xr[lane], v1 = xr[lane + 32], v2 = xr[lane + 64];
        Xs[t * 96 + lane]      = v0;
        Xs[t * 96 + lane + 32] = v1;
        Xs[t * 96 + lane + 64] = v2;
        float s = v0 + v1 + v2;
        #pragma unroll
        for (int o = 16; o; o >>= 1) s += __shfl_xor_sync(~0u, s, o);
        float m = s * (1.f / 96.f);
        float d0 = v0 - m, d1 = v1 - m, d2 = v2 - m;
        float q = d0 * d0 + d1 * d1 + d2 * d2;
        #pragma unroll
        for (int o = 16; o; o >>= 1) q += __shfl_xor_sync(~0u, q, o);
        float rr = rsqrtf(q * (1.f / 96.f) + 1e-5f);
        As[t * 100 + lane]      = __float2bfloat16(d0 * rr * g1[lane]      + bt1[lane]);
        As[t * 100 + lane + 32] = __float2bfloat16(d1 * rr * g1[lane + 32] + bt1[lane + 32]);
        As[t * 100 + lane + 64] = __float2bfloat16(d2 * rr * g1[lane + 64] + bt1[lane + 64]);
    }
    __syncthreads();

    // ---- phase 1: QKV = As @ Wqkv (+bias), 3 segments of 96 cols ----
    #pragma unroll
    for (int seg = 0; seg < 3; seg++) {
        {
            const int4* src = (const int4*)(g_wqkv_bf + (size_t)seg * 9600);
            int4* dst = (int4*)U;
            #pragma unroll
            for (int e = 0; e < 5; e++) {
                int i = e * 256 + tid;
                if (i < 1200) dst[i] = src[i];
            }
        }
        __syncthreads();

        int nw = (wid & 1) * 48;
        float acc[6][4] = {};
        #pragma unroll
        for (int ks = 0; ks < 6; ks++) {
            int kb = ks * 16;
            unsigned a[4];
            a[0] = *(const unsigned*)&As[(mw + g)     * 100 + kb + tig * 2];
            a[1] = *(const unsigned*)&As[(mw + g + 8) * 100 + kb + tig * 2];
            a[2] = *(const unsigned*)&As[(mw + g)     * 100 + kb + 8 + tig * 2];
            a[3] = *(const unsigned*)&As[(mw + g + 8) * 100 + kb + 8 + tig * 2];
            #pragma unroll
            for (int nt = 0; nt < 6; nt++) {
                unsigned b[2];
                int c0 = nw + nt * 8 + g;
                b[0] = *(const unsigned*)&U[c0 * 100 + kb + tig * 2];
                b[1] = *(const unsigned*)&U[c0 * 100 + kb + 8 + tig * 2];
                mma16(acc[nt], a, b);
            }
        }
        #pragma unroll
        for (int nt = 0; nt < 6; nt++) {
            #pragma unroll
            for (int half = 0; half < 2; half++) {
                int t = mw + g + half * 8;
                int c = nw + nt * 8 + tig * 2;
                float v0 = acc[nt][half * 2 + 0] + bqkv[seg * 96 + c];
                float v1 = acc[nt][half * 2 + 1] + bqkv[seg * 96 + c + 1];
                if (seg == 0) {
                    *(__nv_bfloat162*)&Qs[t * 100 + c] =
                        __floats2bfloat162_rn(v0 * SCALE_F, v1 * SCALE_F);
                } else if (seg == 1) {
                    *(__nv_bfloat162*)&Ks[t * 100 + c] =
                        __floats2bfloat162_rn(v0, v1);
                } else {
                    Vt[c * 72 + t]       = __float2bfloat16(v0);
                    Vt[(c + 1) * 72 + t] = __float2bfloat16(v1);
                }
            }
        }
        __syncthreads();
    }

    // ---- phase 2: per-head attention ----
    #pragma unroll
    for (int h = 0; h < 3; h++) {
        int h32 = h * 32;
        // S = Qscaled @ K^T  (warp: 16 rows x 32 cols)
        {
            int nw = (wid & 1) * 32;
            float acc[4][4] = {};
            #pragma unroll
            for (int ks = 0; ks < 2; ks++) {
                int kb = h32 + ks * 16;
                unsigned a[4];
                a[0] = *(const unsigned*)&Qs[(mw + g)     * 100 + kb + tig * 2];
                a[1] = *(const unsigned*)&Qs[(mw + g + 8) * 100 + kb + tig * 2];
                a[2] = *(const unsigned*)&Qs[(mw + g)     * 100 + kb + 8 + tig * 2];
                a[3] = *(const unsigned*)&Qs[(mw + g + 8) * 100 + kb + 8 + tig * 2];
                #pragma unroll
                for (int nt = 0; nt < 4; nt++) {
                    unsigned b[2];
                    int c0 = nw + nt * 8 + g;
                    b[0] = *(const unsigned*)&Ks[c0 * 100 + kb + tig * 2];
                    b[1] = *(const unsigned*)&Ks[c0 * 100 + kb + 8 + tig * 2];
                    mma16(acc[nt], a, b);
                }
            }
            #pragma unroll
            for (int nt = 0; nt < 4; nt++) {
                int cc = nw + nt * 8 + tig * 2;
                Ssm[(mw + g)     * 66 + cc]     = acc[nt][0];
                Ssm[(mw + g)     * 66 + cc + 1] = acc[nt][1];
                Ssm[(mw + g + 8) * 66 + cc]     = acc[nt][2];
                Ssm[(mw + g + 8) * 66 + cc + 1] = acc[nt][3];
            }
        }
        __syncthreads();

        // softmax (8 warps x 8 rows) -> probs gmem + Ps bf16
        #pragma unroll
        for (int rr2 = 0; rr2 < 8; rr2++) {
            int i = wid * 8 + rr2;
            float a0 = Ssm[i * 66 + lane], a1 = Ssm[i * 66 + lane + 32];
            float mx = fmaxf(a0, a1);
            #pragma unroll
            for (int o = 16; o; o >>= 1) mx = fmaxf(mx, __shfl_xor_sync(~0u, mx, o));
            float e0 = __expf(a0 - mx), e1 = __expf(a1 - mx);
            float sm = e0 + e1;
            #pragma unroll
            for (int o = 16; o; o >>= 1) sm += __shfl_xor_sync(~0u, sm, o);
            float inv = 1.f / sm;
            e0 *= inv; e1 *= inv;
            Ps[i * 72 + lane]      = __float2bfloat16(e0);
            Ps[i * 72 + lane + 32] = __float2bfloat16(e1);
            float* ao = attn_out + ((size_t)(w * 3 + h) * 64 + i) * 64;
            ao[lane] = e0; ao[lane + 32] = e1;
        }
        __syncthreads();

        // O = P @ V + LePE -> Os cols [h32, h32+32)  (warp: 16 rows x 16 d)
        {
            int d0 = h32 + (wid & 1) * 16;
            float acc[2][4] = {};
            #pragma unroll
            for (int ks = 0; ks < 4; ks++) {
                int kb = ks * 16;
                unsigned a[4];
                a[0] = *(const unsigned*)&Ps[(mw + g)     * 72 + kb + tig * 2];
                a[1] = *(const unsigned*)&Ps[(mw + g + 8) * 72 + kb + tig * 2];
                a[2] = *(const unsigned*)&Ps[(mw + g)     * 72 + kb + 8 + tig * 2];
                a[3] = *(const unsigned*)&Ps[(mw + g + 8) * 72 + kb + 8 + tig * 2];
                #pragma unroll
                for (int nt = 0; nt < 2; nt++) {
                    unsigned b[2];
                    int c0 = d0 + nt * 8 + g;
                    b[0] = *(const unsigned*)&Vt[c0 * 72 + kb + tig * 2];
                    b[1] = *(const unsigned*)&Vt[c0 * 72 + kb + 8 + tig * 2];
                    mma16(acc[nt], a, b);
                }
            }
            #pragma unroll
            for (int nt = 0; nt < 2; nt++) {
                #pragma unroll
                for (int half = 0; half < 2; half++) {
                    int t = mw + g + half * 8;
                    int gy = t >> 3, gx = t & 7;
                    #pragma unroll
                    for (int e = 0; e < 2; e++) {
                        int d = d0 + nt * 8 + tig * 2 + e;  // global channel
                        float lp = bl[d];
                        #pragma unroll
                        for (int dy = -1; dy <= 1; dy++) {
                            int yy = gy + dy;
                            if (yy < 0 || yy > 7) continue;
                            #pragma unroll
                            for (int dxk = -1; dxk <= 1; dxk++) {
                                int xx = gx + dxk;
                                if (xx < 0 || xx > 7) continue;
                                lp += __bfloat162float(Vt[d * 72 + yy * 8 + xx]) *
                                      wl[d * 9 + (dy + 1) * 3 + (dxk + 1)];
                            }
                        }
                        Os[t * 100 + d] =
                            __float2bfloat16(acc[nt][half * 2 + e] + lp);
                    }
                }
            }
        }
        __syncthreads();
    }

    // ---- phase 3: proj + residual -> x1 kept in Xs (fp32, in place) ----
    {
        const int4* src = (const int4*)g_wproj_bf;
        int4* dst = (int4*)U;
        #pragma unroll
        for (int e = 0; e < 5; e++) {
            int i = e * 256 + tid;
            if (i < 1200) dst[i] = src[i];
        }
    }
    __syncthreads();
    {
        int nw = (wid & 1) * 48;
        float acc[6][4] = {};
        #pragma unroll
        for (int ks = 0; ks < 6; ks++) {
            int kb = ks * 16;
            unsigned a[4];
            a[0] = *(const unsigned*)&Os[(mw + g)     * 100 + kb + tig * 2];
            a[1] = *(const unsigned*)&Os[(mw + g + 8) * 100 + kb + tig * 2];
            a[2] = *(const unsigned*)&Os[(mw + g)     * 100 + kb + 8 + tig * 2];
            a[3] = *(const unsigned*)&Os[(mw + g + 8) * 100 + kb + 8 + tig * 2];
            #pragma unroll
            for (int nt = 0; nt < 6; nt++) {
                unsigned b[2];
                int c0 = nw + nt * 8 + g;
                b[0] = *(const unsigned*)&U[c0 * 100 + kb + tig * 2];
                b[1] = *(const unsigned*)&U[c0 * 100 + kb + 8 + tig * 2];
                mma16(acc[nt], a, b);
            }
        }
        #pragma unroll
        for (int half = 0; half < 2; half++) {
            int t = mw + g + half * 8;
            #pragma unroll
            for (int nt = 0; nt < 6; nt++) {
                int c = nw + nt * 8 + tig * 2;
                Xs[t * 96 + c]     += acc[nt][half * 2 + 0] + bproj[c];
                Xs[t * 96 + c + 1] += acc[nt][half * 2 + 1] + bproj[c + 1];
            }
        }
    }
    __syncthreads();

    // ---- phase 4: MLP (LN2 + FC1 + GELU + FC2 + residual) on resident rows
    // LN2: Xs (x1) -> As bf16
    #pragma unroll
    for (int r = 0; r < 8; r++) {
        int t = wid * 8 + r;
        float v0 = Xs[t * 96 + lane], v1 = Xs[t * 96 + lane + 32],
              v2 = Xs[t * 96 + lane + 64];
        float s = v0 + v1 + v2;
        #pragma unroll
        for (int o = 16; o; o >>= 1) s += __shfl_xor_sync(~0u, s, o);
        float m = s * (1.f / 96.f);
        float d0 = v0 - m, d1 = v1 - m, d2 = v2 - m;
        float q = d0 * d0 + d1 * d1 + d2 * d2;
        #pragma unroll
        for (int o = 16; o; o >>= 1) q += __shfl_xor_sync(~0u, q, o);
        float rr = rsqrtf(q * (1.f / 96.f) + 1e-5f);
        As[t * 100 + lane]      = __float2bfloat16(d0 * rr * g2[lane]      + bt2[lane]);
        As[t * 100 + lane + 32] = __float2bfloat16(d1 * rr * g2[lane + 32] + bt2[lane + 32]);
        As[t * 100 + lane + 64] = __float2bfloat16(d2 * rr * g2[lane + 64] + bt2[lane + 64]);
    }
    __syncthreads();

    float acc2[6][4] = {};
    for (int c = 0; c < 4; c++) {
        {
            const int4* s1 = (const int4*)(g_w1_bf + (size_t)c * 9600);
            const int4* s2 = (const int4*)(g_w2_bf + (size_t)c * 9600);
            int4* d1 = (int4*)U;
            int4* d2 = (int4*)W2s;
            #pragma unroll
            for (int e = 0; e < 5; e++) {
                int i = e * 256 + tid;
                if (i < 1200) { d1[i] = s1[i]; d2[i] = s2[i]; }
            }
        }
        __syncthreads();

        int nw = (wid & 1) * 48;
        // H = As @ W1c
        float accH[6][4] = {};
        #pragma unroll
        for (int ks = 0; ks < 6; ks++) {
            int kb = ks * 16;
            unsigned a[4];
            a[0] = *(const unsigned*)&As[(mw + g)     * 100 + kb + tig * 2];
            a[1] = *(const unsigned*)&As[(mw + g + 8) * 100 + kb + tig * 2];
            a[2] = *(const unsigned*)&As[(mw + g)     * 100 + kb + 8 + tig * 2];
            a[3] = *(const unsigned*)&As[(mw + g + 8) * 100 + kb + 8 + tig * 2];
            #pragma unroll
            for (int nt = 0; nt < 6; nt++) {
                unsigned b[2];
                int c0 = nw + nt * 8 + g;
                b[0] = *(const unsigned*)&U[c0 * 100 + kb + tig * 2];
                b[1] = *(const unsigned*)&U[c0 * 100 + kb + 8 + tig * 2];
                mma16(accH[nt], a, b);
            }
        }
        // bias1 + exact GELU -> Hs
        #pragma unroll
        for (int half = 0; half < 2; half++) {
            int row = mw + g + half * 8;
            #pragma unroll
            for (int nt = 0; nt < 6; nt++) {
                int col = nw + nt * 8 + tig * 2;
                float v0 = accH[nt][half * 2 + 0] + b1[c * 96 + col];
                float v1 = accH[nt][half * 2 + 1] + b1[c * 96 + col + 1];
                v0 = 0.5f * v0 * (1.f + erff(v0 * 0.70710678118f));
                v1 = 0.5f * v1 * (1.f + erff(v1 * 0.70710678118f));
                *(__nv_bfloat162*)&Hs[row * 100 + col] = __floats2bfloat162_rn(v0, v1);
            }
        }
        __syncthreads();

        // acc2 += Hs @ W2c
        #pragma unroll
        for (int ks = 0; ks < 6; ks++) {
            int kb = ks * 16;
            unsigned a[4];
            a[0] = *(const unsigned*)&Hs[(mw + g)     * 100 + kb + tig * 2];
            a[1] = *(const unsigned*)&Hs[(mw + g + 8) * 100 + kb + tig * 2];
            a[2] = *(const unsigned*)&Hs[(mw + g)     * 100 + kb + 8 + tig * 2];
            a[3] = *(const unsigned*)&Hs[(mw + g + 8) * 100 + kb + 8 + tig * 2];
            #pragma unroll
            for (int nt = 0; nt < 6; nt++) {
                unsigned b[2];
                int c0 = nw + nt * 8 + g;
                b[0] = *(const unsigned*)&W2s[c0 * 100 + kb + tig * 2];
                b[1] = *(const unsigned*)&W2s[c0 * 100 + kb + 8 + tig * 2];
                mma16(acc2[nt], a, b);
            }
        }
        __syncthreads();
    }

    // epilogue: out = x1 + mlp
    {
        int nw = (wid & 1) * 48;
        #pragma unroll
        for (int half = 0; half < 2; half++) {
            int t = mw + g + half * 8;
            int tok = win2tok(w * 64 + t);
            #pragma unroll
            for (int nt = 0; nt < 6; nt++) {
                int c = nw + nt * 8 + tig * 2;
                float v0 = acc2[nt][half * 2 + 0] + b2[c]     + Xs[t * 96 + c];
                float v1 = acc2[nt][half * 2 + 1] + b2[c + 1] + Xs[t * 96 + c + 1];
                *(float2*)(out + (size_t)tok * 96 + c) = make_float2(v0, v1);
            }
        }
    }
}

// ---------------- launch ----------------
extern "C" void kernel_launch(void* const* d_in, const int* in_sizes, int n_in,
                              void* d_out, int out_size) {
    const float* x      = (const float*)d_in[0];
    const float* w_qkv  = (const float*)d_in[1];
    const float* b_qkv  = (const float*)d_in[2];
    const float* w_lepe = (const float*)d_in[3];
    const float* b_lepe = (const float*)d_in[4];
    const float* w_proj = (const float*)d_in[5];
    const float* b_proj = (const float*)d_in[6];
    const float* g1     = (const float*)d_in[7];
    const float* bt1    = (const float*)d_in[8];
    const float* g2     = (const float*)d_in[9];
    const float* bt2    = (const float*)d_in[10];
    const float* w_fc1  = (const float*)d_in[11];
    const float* b_fc1  = (const float*)d_in[12];
    const float* w_fc2  = (const float*)d_in[13];
    const float* b_fc2  = (const float*)d_in[14];

    float* out0 = (float*)d_out;

    float* pfb;
    cudaGetSymbolAddress((void**)&pfb, g_attn_fb);

    float* attn_out = (out_size >= OUT0_ELEMS + ATTN_ELEMS)
                        ? (out0 + OUT0_ELEMS) : pfb;

    cudaFuncSetAttribute(block_kernel,
                         cudaFuncAttributeMaxDynamicSharedMemorySize, SM_MEGA);

    // 0. precompute bf16 weights
    prep_weights<<<432, 256>>>(w_qkv, w_proj, w_fc1, w_fc2);

    // 1. fully fused transformer block, one window per block
    block_kernel<<<NW_N, 256, SM_MEGA>>>(x, b_qkv, w_lepe, b_lepe, b_proj,
                                         g1, bt1, g2, bt2, b_fc1, b_fc2,
                                         out0, attn_out);
}

// round 8
// speedup vs baseline: 1.4833x; 1.4833x over previous
#include <cuda_runtime.h>
#include <cuda_bf16.h>
#include <math.h>

// ---------------- problem constants ----------------
#define B_N   32
#define L_N   4096
#define C_N   96
#define GG_N  64
#define NW_N  2048
#define T_N   131072
#define HID_N 384

#define OUT0_ELEMS (T_N * C_N)
#define ATTN_ELEMS (NW_N * 3 * GG_N * GG_N)

#define SCALE_F 0.17677669529663687f  // 32^-0.5

// ---------------- scratch ----------------
__device__ float g_attn_fb[ATTN_ELEMS];  // fallback sink for attn probs

// fragment-packed bf16 weights: per (n8-tile, ks): 32 lanes x uint2
// word0 = pack(W[k0][n], W[k0+1][n]), word1 = pack(W[k0+8][n], W[k0+9][n])
// with n = n8*8 + (lane>>2), k0 = ks*16 + (lane&3)*2
__device__ uint2 g_wqkv_p[36 * 6 * 32];      // N=288
__device__ uint2 g_wproj_p[12 * 6 * 32];     // N=96
__device__ uint2 g_w1_p[48 * 6 * 32];        // N=384
__device__ uint2 g_w2_p[4 * 12 * 6 * 32];    // 4 chunks, N=96 each

__device__ __forceinline__ unsigned packbf(float a, float b) {
    __nv_bfloat162 t = __floats2bfloat162_rn(a, b);
    return *(unsigned*)&t;
}

// jobs: qkv 6912, proj 2304, w1 9216, w2 9216  (total 27648)
__global__ void prep_weights(const float* __restrict__ wqkv,
                             const float* __restrict__ wproj,
                             const float* __restrict__ w1,
                             const float* __restrict__ w2) {
    int i = blockIdx.x * 256 + threadIdx.x;
    const float* src;
    uint2* dst;
    int ld, kbase = 0, idx;
    if (i < 6912)              { src = wqkv;  dst = g_wqkv_p;  ld = 288; idx = i; }
    else if (i < 9216)         { src = wproj; dst = g_wproj_p; ld = 96;  idx = i - 6912; }
    else if (i < 18432)        { src = w1;    dst = g_w1_p;    ld = 384; idx = i - 9216; }
    else                       {
        int j = i - 18432;
        int c = j / 2304;
        src = w2; dst = g_w2_p + c * 2304; ld = 96; kbase = c * 96; idx = j - c * 2304;
    }
    int q = idx >> 5, lane = idx & 31;
    int n8 = q / 6, ks = q - n8 * 6;
    int g = lane >> 2, tig = lane & 3;
    int n = n8 * 8 + g;
    int k0 = kbase + ks * 16 + tig * 2;
    uint2 v;
    v.x = packbf(src[(size_t)k0 * ld + n],       src[(size_t)(k0 + 1) * ld + n]);
    v.y = packbf(src[(size_t)(k0 + 8) * ld + n], src[(size_t)(k0 + 9) * ld + n]);
    dst[q * 32 + lane] = v;
}

__device__ __forceinline__ int win2tok(int m) {
    int w = m >> 6, t = m & 63;
    int b = w >> 6, rem = w & 63;
    int hy = rem >> 3, wx = rem & 7;
    int gy = t >> 3,  gx = t & 7;
    return b * L_N + (hy * 8 + gy) * 64 + (wx * 8 + gx);
}

__device__ __forceinline__ void mma16(float* c, const unsigned* a, const unsigned* b) {
    asm volatile(
        "mma.sync.aligned.m16n8k16.row.col.f32.bf16.bf16.f32 "
        "{%0,%1,%2,%3}, {%4,%5,%6,%7}, {%8,%9}, {%0,%1,%2,%3};\n"
        : "+f"(c[0]), "+f"(c[1]), "+f"(c[2]), "+f"(c[3])
        : "r"(a[0]), "r"(a[1]), "r"(a[2]), "r"(a[3]), "r"(b[0]), "r"(b[1]));
}

// ---------------- smem layout (bytes) ----------------
#define SM_AS  0        // 12800: As (LN out, stride 100) / Ps (probs, stride 72)
#define SM_QS  12800    // 12800: Q scaled, stride 100
#define SM_KS  25600    // 12800: K, stride 100
#define SM_VT  38400    // 13824: V^T [c][t], stride 72
#define SM_OS  52224    // 12800: attn-out+lepe (stride 100) / Hs (gelu hidden)
#define SM_XC  65024    // 1024:  softmax exchange float[2][64][2]
#define SM_TOT 66048

__global__ __launch_bounds__(256, 3)
void block_kernel(const float* __restrict__ x,
                  const float* __restrict__ bqkv,
                  const float* __restrict__ wl,
                  const float* __restrict__ bl,
                  const float* __restrict__ bproj,
                  const float* __restrict__ g1,
                  const float* __restrict__ bt1,
                  const float* __restrict__ g2,
                  const float* __restrict__ bt2,
                  const float* __restrict__ b1,
                  const float* __restrict__ b2,
                  float* __restrict__ out,
                  float* __restrict__ attn_out) {
    extern __shared__ char smraw[];
    __nv_bfloat16* As = (__nv_bfloat16*)(smraw + SM_AS);
    __nv_bfloat16* Ps = (__nv_bfloat16*)(smraw + SM_AS);
    __nv_bfloat16* Qs = (__nv_bfloat16*)(smraw + SM_QS);
    __nv_bfloat16* Ks = (__nv_bfloat16*)(smraw + SM_KS);
    __nv_bfloat16* Vt = (__nv_bfloat16*)(smraw + SM_VT);
    __nv_bfloat16* Os = (__nv_bfloat16*)(smraw + SM_OS);
    __nv_bfloat16* Hs = (__nv_bfloat16*)(smraw + SM_OS);
    float*         Xc = (float*)(smraw + SM_XC);

    int w = blockIdx.x;
    int tid = threadIdx.x, lane = tid & 31, wid = tid >> 5;
    int g = lane >> 2, tig = lane & 3;
    int mw = (wid >> 1) * 16, wh = wid & 1;

    // ---- phase 0: LN1(x window rows) -> As bf16 ----
    #pragma unroll
    for (int r = 0; r < 8; r++) {
        int t = wid * 8 + r;
        const float* xr = x + (size_t)win2tok(w * 64 + t) * 96;
        float v0 = xr[lane], v1 = xr[lane + 32], v2 = xr[lane + 64];
        float s = v0 + v1 + v2;
        #pragma unroll
        for (int o = 16; o; o >>= 1) s += __shfl_xor_sync(~0u, s, o);
        float m = s * (1.f / 96.f);
        float d0 = v0 - m, d1 = v1 - m, d2 = v2 - m;
        float q = d0 * d0 + d1 * d1 + d2 * d2;
        #pragma unroll
        for (int o = 16; o; o >>= 1) q += __shfl_xor_sync(~0u, q, o);
        float rr = rsqrtf(q * (1.f / 96.f) + 1e-5f);
        As[t * 100 + lane]      = __float2bfloat16(d0 * rr * g1[lane]      + bt1[lane]);
        As[t * 100 + lane + 32] = __float2bfloat16(d1 * rr * g1[lane + 32] + bt1[lane + 32]);
        As[t * 100 + lane + 64] = __float2bfloat16(d2 * rr * g1[lane + 64] + bt1[lane + 64]);
    }
    __syncthreads();

    // ---- phase 1: QKV (b-frags via LDG from packed weights) ----
    #pragma unroll
    for (int seg = 0; seg < 3; seg++) {
        int nw = wh * 48;
        float acc[6][4] = {};
        #pragma unroll
        for (int ks = 0; ks < 6; ks++) {
            int kb = ks * 16;
            unsigned a[4];
            a[0] = *(const unsigned*)&As[(mw + g)     * 100 + kb + tig * 2];
            a[1] = *(const unsigned*)&As[(mw + g + 8) * 100 + kb + tig * 2];
            a[2] = *(const unsigned*)&As[(mw + g)     * 100 + kb + 8 + tig * 2];
            a[3] = *(const unsigned*)&As[(mw + g + 8) * 100 + kb + 8 + tig * 2];
            #pragma unroll
            for (int nt = 0; nt < 6; nt++) {
                int n8 = seg * 12 + wh * 6 + nt;
                uint2 v = __ldg(&g_wqkv_p[(n8 * 6 + ks) * 32 + lane]);
                mma16(acc[nt], a, (const unsigned*)&v);
            }
        }
        #pragma unroll
        for (int nt = 0; nt < 6; nt++) {
            #pragma unroll
            for (int half = 0; half < 2; half++) {
                int t = mw + g + half * 8;
                int c = nw + nt * 8 + tig * 2;
                float v0 = acc[nt][half * 2 + 0] + bqkv[seg * 96 + c];
                float v1 = acc[nt][half * 2 + 1] + bqkv[seg * 96 + c + 1];
                if (seg == 0) {
                    *(__nv_bfloat162*)&Qs[t * 100 + c] =
                        __floats2bfloat162_rn(v0 * SCALE_F, v1 * SCALE_F);
                } else if (seg == 1) {
                    *(__nv_bfloat162*)&Ks[t * 100 + c] =
                        __floats2bfloat162_rn(v0, v1);
                } else {
                    Vt[c * 72 + t]       = __float2bfloat16(v0);
                    Vt[(c + 1) * 72 + t] = __float2bfloat16(v1);
                }
            }
        }
    }
    __syncthreads();

    // ---- phase 2: per-head attention with register softmax ----
    #pragma unroll
    for (int h = 0; h < 3; h++) {
        int h32 = h * 32;
        int nw2 = wh * 32;
        // S = Qs @ Ks^T in registers (warp: 16 rows x 32 cols)
        float sacc[4][4] = {};
        #pragma unroll
        for (int ks = 0; ks < 2; ks++) {
            int kb = h32 + ks * 16;
            unsigned a[4];
            a[0] = *(const unsigned*)&Qs[(mw + g)     * 100 + kb + tig * 2];
            a[1] = *(const unsigned*)&Qs[(mw + g + 8) * 100 + kb + tig * 2];
            a[2] = *(const unsigned*)&Qs[(mw + g)     * 100 + kb + 8 + tig * 2];
            a[3] = *(const unsigned*)&Qs[(mw + g + 8) * 100 + kb + 8 + tig * 2];
            #pragma unroll
            for (int nt = 0; nt < 4; nt++) {
                unsigned b[2];
                int c0 = nw2 + nt * 8 + g;
                b[0] = *(const unsigned*)&Ks[c0 * 100 + kb + tig * 2];
                b[1] = *(const unsigned*)&Ks[c0 * 100 + kb + 8 + tig * 2];
                mma16(sacc[nt], a, b);
            }
        }
        // own-half rowmax (rows r0=mw+g, r1=mw+g+8)
        float m0 = -1e30f, m1 = -1e30f;
        #pragma unroll
        for (int nt = 0; nt < 4; nt++) {
            m0 = fmaxf(m0, fmaxf(sacc[nt][0], sacc[nt][1]));
            m1 = fmaxf(m1, fmaxf(sacc[nt][2], sacc[nt][3]));
        }
        m0 = fmaxf(m0, __shfl_xor_sync(~0u, m0, 1));
        m0 = fmaxf(m0, __shfl_xor_sync(~0u, m0, 2));
        m1 = fmaxf(m1, __shfl_xor_sync(~0u, m1, 1));
        m1 = fmaxf(m1, __shfl_xor_sync(~0u, m1, 2));
        float e[4][4];
        float s0 = 0.f, s1 = 0.f;
        #pragma unroll
        for (int nt = 0; nt < 4; nt++) {
            e[nt][0] = __expf(sacc[nt][0] - m0);
            e[nt][1] = __expf(sacc[nt][1] - m0);
            e[nt][2] = __expf(sacc[nt][2] - m1);
            e[nt][3] = __expf(sacc[nt][3] - m1);
            s0 += e[nt][0] + e[nt][1];
            s1 += e[nt][2] + e[nt][3];
        }
        s0 += __shfl_xor_sync(~0u, s0, 1); s0 += __shfl_xor_sync(~0u, s0, 2);
        s1 += __shfl_xor_sync(~0u, s1, 1); s1 += __shfl_xor_sync(~0u, s1, 2);
        if (tig == 0) {
            *(float2*)&Xc[(wh * 64 + mw + g) * 2]     = make_float2(m0, s0);
            *(float2*)&Xc[(wh * 64 + mw + g + 8) * 2] = make_float2(m1, s1);
        }
        __syncthreads();
        float2 o0 = *(float2*)&Xc[((1 ^ wh) * 64 + mw + g) * 2];
        float2 o1 = *(float2*)&Xc[((1 ^ wh) * 64 + mw + g + 8) * 2];
        float M0 = fmaxf(m0, o0.x);
        float sc0 = __expf(m0 - M0) / (s0 * __expf(m0 - M0) + o0.y * __expf(o0.x - M0));
        float M1 = fmaxf(m1, o1.x);
        float sc1 = __expf(m1 - M1) / (s1 * __expf(m1 - M1) + o1.y * __expf(o1.x - M1));
        // write probs (gmem) + Ps (bf16, stride 72)
        {
            float* ao = attn_out + (size_t)((w * 3 + h) * 64) * 64;
            #pragma unroll
            for (int nt = 0; nt < 4; nt++) {
                int c = nw2 + nt * 8 + tig * 2;
                float p00 = e[nt][0] * sc0, p01 = e[nt][1] * sc0;
                float p10 = e[nt][2] * sc1, p11 = e[nt][3] * sc1;
                *(__nv_bfloat162*)&Ps[(mw + g) * 72 + c]     = __floats2bfloat162_rn(p00, p01);
                *(__nv_bfloat162*)&Ps[(mw + g + 8) * 72 + c] = __floats2bfloat162_rn(p10, p11);
                *(float2*)&ao[(size_t)(mw + g) * 64 + c]     = make_float2(p00, p01);
                *(float2*)&ao[(size_t)(mw + g + 8) * 64 + c] = make_float2(p10, p11);
            }
        }
        __syncthreads();

        // O = P @ V + LePE -> Os cols [h32, h32+32)
        {
            int d0 = h32 + wh * 16;
            float pacc[2][4] = {};
            #pragma unroll
            for (int ks = 0; ks < 4; ks++) {
                int kb = ks * 16;
                unsigned a[4];
                a[0] = *(const unsigned*)&Ps[(mw + g)     * 72 + kb + tig * 2];
                a[1] = *(const unsigned*)&Ps[(mw + g + 8) * 72 + kb + tig * 2];
                a[2] = *(const unsigned*)&Ps[(mw + g)     * 72 + kb + 8 + tig * 2];
                a[3] = *(const unsigned*)&Ps[(mw + g + 8) * 72 + kb + 8 + tig * 2];
                #pragma unroll
                for (int nt = 0; nt < 2; nt++) {
                    unsigned b[2];
                    int c0 = d0 + nt * 8 + g;
                    b[0] = *(const unsigned*)&Vt[c0 * 72 + kb + tig * 2];
                    b[1] = *(const unsigned*)&Vt[c0 * 72 + kb + 8 + tig * 2];
                    mma16(pacc[nt], a, b);
                }
            }
            #pragma unroll
            for (int nt = 0; nt < 2; nt++) {
                #pragma unroll
                for (int half = 0; half < 2; half++) {
                    int t = mw + g + half * 8;
                    int gy = t >> 3, gx = t & 7;
                    #pragma unroll
                    for (int ee = 0; ee < 2; ee++) {
                        int d = d0 + nt * 8 + tig * 2 + ee;
                        float lp = bl[d];
                        #pragma unroll
                        for (int dy = -1; dy <= 1; dy++) {
                            int yy = gy + dy;
                            if (yy < 0 || yy > 7) continue;
                            #pragma unroll
                            for (int dxk = -1; dxk <= 1; dxk++) {
                                int xx = gx + dxk;
                                if (xx < 0 || xx > 7) continue;
                                lp += __bfloat162float(Vt[d * 72 + yy * 8 + xx]) *
                                      wl[d * 9 + (dy + 1) * 3 + (dxk + 1)];
                            }
                        }
                        Os[t * 100 + d] = __float2bfloat16(pacc[nt][half * 2 + ee] + lp);
                    }
                }
            }
        }
        __syncthreads();
    }

    // ---- phase 3: proj + residual(x from gmem) -> x1 staged in out gmem ----
    {
        int nw = wh * 48;
        float acc[6][4] = {};
        #pragma unroll
        for (int ks = 0; ks < 6; ks++) {
            int kb = ks * 16;
            unsigned a[4];
            a[0] = *(const unsigned*)&Os[(mw + g)     * 100 + kb + tig * 2];
            a[1] = *(const unsigned*)&Os[(mw + g + 8) * 100 + kb + tig * 2];
            a[2] = *(const unsigned*)&Os[(mw + g)     * 100 + kb + 8 + tig * 2];
            a[3] = *(const unsigned*)&Os[(mw + g + 8) * 100 + kb + 8 + tig * 2];
            #pragma unroll
            for (int nt = 0; nt < 6; nt++) {
                int n8 = wh * 6 + nt;
                uint2 v = __ldg(&g_wproj_p[(n8 * 6 + ks) * 32 + lane]);
                mma16(acc[nt], a, (const unsigned*)&v);
            }
        }
        #pragma unroll
        for (int half = 0; half < 2; half++) {
            int t = mw + g + half * 8;
            int tok = win2tok(w * 64 + t);
            #pragma unroll
            for (int nt = 0; nt < 6; nt++) {
                int c = nw + nt * 8 + tig * 2;
                float2 xr = __ldg((const float2*)&x[(size_t)tok * 96 + c]);
                float v0 = acc[nt][half * 2 + 0] + bproj[c]     + xr.x;
                float v1 = acc[nt][half * 2 + 1] + bproj[c + 1] + xr.y;
                *(float2*)(out + (size_t)tok * 96 + c) = make_float2(v0, v1);
            }
        }
    }
    __syncthreads();

    // ---- phase 4a: LN2 (x1 rows from out gmem) -> As ----
    #pragma unroll
    for (int r = 0; r < 8; r++) {
        int t = wid * 8 + r;
        const float* xr = out + (size_t)win2tok(w * 64 + t) * 96;
        float v0 = xr[lane], v1 = xr[lane + 32], v2 = xr[lane + 64];
        float s = v0 + v1 + v2;
        #pragma unroll
        for (int o = 16; o; o >>= 1) s += __shfl_xor_sync(~0u, s, o);
        float m = s * (1.f / 96.f);
        float d0 = v0 - m, d1 = v1 - m, d2 = v2 - m;
        float q = d0 * d0 + d1 * d1 + d2 * d2;
        #pragma unroll
        for (int o = 16; o; o >>= 1) q += __shfl_xor_sync(~0u, q, o);
        float rr = rsqrtf(q * (1.f / 96.f) + 1e-5f);
        As[t * 100 + lane]      = __float2bfloat16(d0 * rr * g2[lane]      + bt2[lane]);
        As[t * 100 + lane + 32] = __float2bfloat16(d1 * rr * g2[lane + 32] + bt2[lane + 32]);
        As[t * 100 + lane + 64] = __float2bfloat16(d2 * rr * g2[lane + 64] + bt2[lane + 64]);
    }
    __syncthreads();

    // ---- phase 4b: MLP chunks ----
    float acc2[6][4] = {};
    int nw = wh * 48;
    for (int c = 0; c < 4; c++) {
        float accH[6][4] = {};
        #pragma unroll
        for (int ks = 0; ks < 6; ks++) {
            int kb = ks * 16;
            unsigned a[4];
            a[0] = *(const unsigned*)&As[(mw + g)     * 100 + kb + tig * 2];
            a[1] = *(const unsigned*)&As[(mw + g + 8) * 100 + kb + tig * 2];
            a[2] = *(const unsigned*)&As[(mw + g)     * 100 + kb + 8 + tig * 2];
            a[3] = *(const unsigned*)&As[(mw + g + 8) * 100 + kb + 8 + tig * 2];
            #pragma unroll
            for (int nt = 0; nt < 6; nt++) {
                int n8 = c * 12 + wh * 6 + nt;
                uint2 v = __ldg(&g_w1_p[(n8 * 6 + ks) * 32 + lane]);
                mma16(accH[nt], a, (const unsigned*)&v);
            }
        }
        // bias1 + exact GELU -> Hs
        #pragma unroll
        for (int half = 0; half < 2; half++) {
            int row = mw + g + half * 8;
            #pragma unroll
            for (int nt = 0; nt < 6; nt++) {
                int col = nw + nt * 8 + tig * 2;
                float v0 = accH[nt][half * 2 + 0] + b1[c * 96 + col];
                float v1 = accH[nt][half * 2 + 1] + b1[c * 96 + col + 1];
                v0 = 0.5f * v0 * (1.f + erff(v0 * 0.70710678118f));
                v1 = 0.5f * v1 * (1.f + erff(v1 * 0.70710678118f));
                *(__nv_bfloat162*)&Hs[row * 100 + col] = __floats2bfloat162_rn(v0, v1);
            }
        }
        __syncthreads();

        #pragma unroll
        for (int ks = 0; ks < 6; ks++) {
            int kb = ks * 16;
            unsigned a[4];
            a[0] = *(const unsigned*)&Hs[(mw + g)     * 100 + kb + tig * 2];
            a[1] = *(const unsigned*)&Hs[(mw + g + 8) * 100 + kb + tig * 2];
            a[2] = *(const unsigned*)&Hs[(mw + g)     * 100 + kb + 8 + tig * 2];
            a[3] = *(const unsigned*)&Hs[(mw + g + 8) * 100 + kb + 8 + tig * 2];
            #pragma unroll
            for (int nt = 0; nt < 6; nt++) {
                int n8 = wh * 6 + nt;
                uint2 v = __ldg(&g_w2_p[c * 2304 + (n8 * 6 + ks) * 32 + lane]);
                mma16(acc2[nt], a, (const unsigned*)&v);
            }
        }
        __syncthreads();
    }

    // epilogue: out = x1(out gmem) + mlp + b2
    #pragma unroll
    for (int half = 0; half < 2; half++) {
        int t = mw + g + half * 8;
        int tok = win2tok(w * 64 + t);
        #pragma unroll
        for (int nt = 0; nt < 6; nt++) {
            int c = nw + nt * 8 + tig * 2;
            float2 x1r = __ldg((const float2*)&out[(size_t)tok * 96 + c]);
            float v0 = acc2[nt][half * 2 + 0] + b2[c]     + x1r.x;
            float v1 = acc2[nt][half * 2 + 1] + b2[c + 1] + x1r.y;
            *(float2*)(out + (size_t)tok * 96 + c) = make_float2(v0, v1);
        }
    }
}

// ---------------- launch ----------------
extern "C" void kernel_launch(void* const* d_in, const int* in_sizes, int n_in,
                              void* d_out, int out_size) {
    const float* x      = (const float*)d_in[0];
    const float* w_qkv  = (const float*)d_in[1];
    const float* b_qkv  = (const float*)d_in[2];
    const float* w_lepe = (const float*)d_in[3];
    const float* b_lepe = (const float*)d_in[4];
    const float* w_proj = (const float*)d_in[5];
    const float* b_proj = (const float*)d_in[6];
    const float* g1     = (const float*)d_in[7];
    const float* bt1    = (const float*)d_in[8];
    const float* g2     = (const float*)d_in[9];
    const float* bt2    = (const float*)d_in[10];
    const float* w_fc1  = (const float*)d_in[11];
    const float* b_fc1  = (const float*)d_in[12];
    const float* w_fc2  = (const float*)d_in[13];
    const float* b_fc2  = (const float*)d_in[14];

    float* out0 = (float*)d_out;

    float* pfb;
    cudaGetSymbolAddress((void**)&pfb, g_attn_fb);

    float* attn_out = (out_size >= OUT0_ELEMS + ATTN_ELEMS)
                        ? (out0 + OUT0_ELEMS) : pfb;

    cudaFuncSetAttribute(block_kernel,
                         cudaFuncAttributeMaxDynamicSharedMemorySize, SM_TOT);

    // 0. pack weights into mma b-fragment order (27648 jobs)
    prep_weights<<<108, 256>>>(w_qkv, w_proj, w_fc1, w_fc2);

    // 1. fully fused transformer block, one window per block
    block_kernel<<<NW_N, 256, SM_TOT>>>(x, b_qkv, w_lepe, b_lepe, b_proj,
                                        g1, bt1, g2, bt2, b_fc1, b_fc2,
                                        out0, attn_out);
}

// round 10
// speedup vs baseline: 1.6061x; 1.0828x over previous
#include <cuda_runtime.h>
#include <cuda_bf16.h>
#include <math.h>

// ---------------- problem constants ----------------
#define B_N   32
#define L_N   4096
#define C_N   96
#define GG_N  64
#define NW_N  2048
#define T_N   131072
#define HID_N 384

#define OUT0_ELEMS (T_N * C_N)
#define ATTN_ELEMS (NW_N * 3 * GG_N * GG_N)

#define SCALE_F 0.17677669529663687f  // 32^-0.5

// ---------------- scratch ----------------
__device__ float g_attn_fb[ATTN_ELEMS];  // fallback sink for attn probs

// fragment-packed bf16 weights: per (n8-tile, ks): 32 lanes x uint2
__device__ uint2 g_wqkv_p[36 * 6 * 32];      // N=288
__device__ uint2 g_wproj_p[12 * 6 * 32];     // N=96
__device__ uint2 g_w1_p[48 * 6 * 32];        // N=384
__device__ uint2 g_w2_p[4 * 12 * 6 * 32];    // 4 chunks, N=96 each

__device__ __forceinline__ unsigned packbf(float a, float b) {
    __nv_bfloat162 t = __floats2bfloat162_rn(a, b);
    return *(unsigned*)&t;
}

// jobs: qkv 6912, proj 2304, w1 9216, w2 9216  (total 27648)
__global__ void prep_weights(const float* __restrict__ wqkv,
                             const float* __restrict__ wproj,
                             const float* __restrict__ w1,
                             const float* __restrict__ w2) {
    int i = blockIdx.x * 256 + threadIdx.x;
    const float* src;
    uint2* dst;
    int ld, kbase = 0, idx;
    if (i < 6912)              { src = wqkv;  dst = g_wqkv_p;  ld = 288; idx = i; }
    else if (i < 9216)         { src = wproj; dst = g_wproj_p; ld = 96;  idx = i - 6912; }
    else if (i < 18432)        { src = w1;    dst = g_w1_p;    ld = 384; idx = i - 9216; }
    else                       {
        int j = i - 18432;
        int c = j / 2304;
        src = w2; dst = g_w2_p + c * 2304; ld = 96; kbase = c * 96; idx = j - c * 2304;
    }
    int q = idx >> 5, lane = idx & 31;
    int n8 = q / 6, ks = q - n8 * 6;
    int g = lane >> 2, tig = lane & 3;
    int n = n8 * 8 + g;
    int k0 = kbase + ks * 16 + tig * 2;
    uint2 v;
    v.x = packbf(src[(size_t)k0 * ld + n],       src[(size_t)(k0 + 1) * ld + n]);
    v.y = packbf(src[(size_t)(k0 + 8) * ld + n], src[(size_t)(k0 + 9) * ld + n]);
    dst[q * 32 + lane] = v;
}

__device__ __forceinline__ int win2tok(int m) {
    int w = m >> 6, t = m & 63;
    int b = w >> 6, rem = w & 63;
    int hy = rem >> 3, wx = rem & 7;
    int gy = t >> 3,  gx = t & 7;
    return b * L_N + (hy * 8 + gy) * 64 + (wx * 8 + gx);
}

__device__ __forceinline__ void mma16(float* c, const unsigned* a, const unsigned* b) {
    asm volatile(
        "mma.sync.aligned.m16n8k16.row.col.f32.bf16.bf16.f32 "
        "{%0,%1,%2,%3}, {%4,%5,%6,%7}, {%8,%9}, {%0,%1,%2,%3};\n"
        : "+f"(c[0]), "+f"(c[1]), "+f"(c[2]), "+f"(c[3])
        : "r"(a[0]), "r"(a[1]), "r"(a[2]), "r"(a[3]), "r"(b[0]), "r"(b[1]));
}

// unpack 8 bf16 (16B-aligned) into 8 floats via one LDS.128
__device__ __forceinline__ void load8bf(float* dst, const __nv_bfloat16* p) {
    uint4 u = *(const uint4*)p;
    __nv_bfloat162 b0 = *(__nv_bfloat162*)&u.x;
    __nv_bfloat162 b1 = *(__nv_bfloat162*)&u.y;
    __nv_bfloat162 b2 = *(__nv_bfloat162*)&u.z;
    __nv_bfloat162 b3 = *(__nv_bfloat162*)&u.w;
    dst[0] = __low2float(b0); dst[1] = __high2float(b0);
    dst[2] = __low2float(b1); dst[3] = __high2float(b1);
    dst[4] = __low2float(b2); dst[5] = __high2float(b2);
    dst[6] = __low2float(b3); dst[7] = __high2float(b3);
}

// ---------------- smem layout (bytes) ----------------
#define SM_AS  0        // 12800: As (LN out, stride 100) / Ps (probs, stride 72)
#define SM_QS  12800    // 12800: Q scaled, stride 100
#define SM_KS  25600    // 12800: K, stride 100
#define SM_VT  38400    // 13824: V^T [c][t], stride 72
#define SM_OS  52224    // 12800: lepe-init then attn-out (stride 100) / Hs
#define SM_XC  65024    // 1024:  softmax exchange float[2][64][2]
#define SM_TOT 66048

__global__ __launch_bounds__(256, 3)
void block_kernel(const float* __restrict__ x,
                  const float* __restrict__ bqkv,
                  const float* __restrict__ wl,
                  const float* __restrict__ bl,
                  const float* __restrict__ bproj,
                  const float* __restrict__ g1,
                  const float* __restrict__ bt1,
                  const float* __restrict__ g2,
                  const float* __restrict__ bt2,
                  const float* __restrict__ b1,
                  const float* __restrict__ b2,
                  float* __restrict__ out,
                  float* __restrict__ attn_out) {
    extern __shared__ char smraw[];
    __nv_bfloat16* As = (__nv_bfloat16*)(smraw + SM_AS);
    __nv_bfloat16* Ps = (__nv_bfloat16*)(smraw + SM_AS);
    __nv_bfloat16* Qs = (__nv_bfloat16*)(smraw + SM_QS);
    __nv_bfloat16* Ks = (__nv_bfloat16*)(smraw + SM_KS);
    __nv_bfloat16* Vt = (__nv_bfloat16*)(smraw + SM_VT);
    __nv_bfloat16* Os = (__nv_bfloat16*)(smraw + SM_OS);
    __nv_bfloat16* Hs = (__nv_bfloat16*)(smraw + SM_OS);
    float*         Xc = (float*)(smraw + SM_XC);

    int w = blockIdx.x;
    int tid = threadIdx.x, lane = tid & 31, wid = tid >> 5;
    int g = lane >> 2, tig = lane & 3;
    int mw = (wid >> 1) * 16, wh = wid & 1;

    // ---- phase 0: LN1(x window rows) -> As bf16 ----
    #pragma unroll
    for (int r = 0; r < 8; r++) {
        int t = wid * 8 + r;
        const float* xr = x + (size_t)win2tok(w * 64 + t) * 96;
        float v0 = xr[lane], v1 = xr[lane + 32], v2 = xr[lane + 64];
        float s = v0 + v1 + v2;
        #pragma unroll
        for (int o = 16; o; o >>= 1) s += __shfl_xor_sync(~0u, s, o);
        float m = s * (1.f / 96.f);
        float d0 = v0 - m, d1 = v1 - m, d2 = v2 - m;
        float q = d0 * d0 + d1 * d1 + d2 * d2;
        #pragma unroll
        for (int o = 16; o; o >>= 1) q += __shfl_xor_sync(~0u, q, o);
        float rr = rsqrtf(q * (1.f / 96.f) + 1e-5f);
        As[t * 100 + lane]      = __float2bfloat16(d0 * rr * g1[lane]      + bt1[lane]);
        As[t * 100 + lane + 32] = __float2bfloat16(d1 * rr * g1[lane + 32] + bt1[lane + 32]);
        As[t * 100 + lane + 64] = __float2bfloat16(d2 * rr * g1[lane + 64] + bt1[lane + 64]);
    }
    __syncthreads();

    // ---- phase 1: QKV (b-frags via LDG from packed weights) ----
    #pragma unroll
    for (int seg = 0; seg < 3; seg++) {
        int nw = wh * 48;
        float acc[6][4] = {};
        #pragma unroll
        for (int ks = 0; ks < 6; ks++) {
            int kb = ks * 16;
            unsigned a[4];
            a[0] = *(const unsigned*)&As[(mw + g)     * 100 + kb + tig * 2];
            a[1] = *(const unsigned*)&As[(mw + g + 8) * 100 + kb + tig * 2];
            a[2] = *(const unsigned*)&As[(mw + g)     * 100 + kb + 8 + tig * 2];
            a[3] = *(const unsigned*)&As[(mw + g + 8) * 100 + kb + 8 + tig * 2];
            #pragma unroll
            for (int nt = 0; nt < 6; nt++) {
                int n8 = seg * 12 + wh * 6 + nt;
                uint2 v = __ldg(&g_wqkv_p[(n8 * 6 + ks) * 32 + lane]);
                mma16(acc[nt], a, (const unsigned*)&v);
            }
        }
        #pragma unroll
        for (int nt = 0; nt < 6; nt++) {
            #pragma unroll
            for (int half = 0; half < 2; half++) {
                int t = mw + g + half * 8;
                int c = nw + nt * 8 + tig * 2;
                float v0 = acc[nt][half * 2 + 0] + bqkv[seg * 96 + c];
                float v1 = acc[nt][half * 2 + 1] + bqkv[seg * 96 + c + 1];
                if (seg == 0) {
                    *(__nv_bfloat162*)&Qs[t * 100 + c] =
                        __floats2bfloat162_rn(v0 * SCALE_F, v1 * SCALE_F);
                } else if (seg == 1) {
                    *(__nv_bfloat162*)&Ks[t * 100 + c] =
                        __floats2bfloat162_rn(v0, v1);
                } else {
                    Vt[c * 72 + t]       = __float2bfloat16(v0);
                    Vt[(c + 1) * 72 + t] = __float2bfloat16(v1);
                }
            }
        }
    }
    __syncthreads();

    // ---- phase 1.5: LePE init: Os[t][d] = bf16(bl[d] + conv3x3(V_d)) ----
    // 768 rows (96 d x 8 gy), 3 per thread; V rows via LDS.128.
    // Visibility to the head-loop RMW is ordered by the Ps sync in head 0.
    #pragma unroll
    for (int j = 0; j < 3; j++) {
        int r = tid * 3 + j;
        int d = r >> 3, gy = r & 7;
        const float* wr = wl + d * 9;
        float w00 = wr[0], w01 = wr[1], w02 = wr[2];
        float w10 = wr[3], w11 = wr[4], w12 = wr[5];
        float w20 = wr[6], w21 = wr[7], w22 = wr[8];
        const __nv_bfloat16* vb = Vt + d * 72;
        float vt[8], vm[8], vbo[8];
        load8bf(vm, vb + gy * 8);
        if (gy > 0) {
            load8bf(vt, vb + (gy - 1) * 8);
        } else {
            for (int q2 = 0; q2 < 8; q2++) vt[q2] = 0.f;
        }
        if (gy < 7) {
            load8bf(vbo, vb + (gy + 1) * 8);
        } else {
            for (int q2 = 0; q2 < 8; q2++) vbo[q2] = 0.f;
        }
        float base = bl[d];
        #pragma unroll
        for (int gx = 0; gx < 8; gx++) {
            float o = base + vt[gx] * w01 + vm[gx] * w11 + vbo[gx] * w21;
            if (gx > 0) o += vt[gx - 1] * w00 + vm[gx - 1] * w10 + vbo[gx - 1] * w20;
            if (gx < 7) o += vt[gx + 1] * w02 + vm[gx + 1] * w12 + vbo[gx + 1] * w22;
            Os[(gy * 8 + gx) * 100 + d] = __float2bfloat16(o);
        }
    }

    // ---- phase 2: per-head attention with register softmax ----
    #pragma unroll
    for (int h = 0; h < 3; h++) {
        int h32 = h * 32;
        int nw2 = wh * 32;
        float sacc[4][4] = {};
        #pragma unroll
        for (int ks = 0; ks < 2; ks++) {
            int kb = h32 + ks * 16;
            unsigned a[4];
            a[0] = *(const unsigned*)&Qs[(mw + g)     * 100 + kb + tig * 2];
            a[1] = *(const unsigned*)&Qs[(mw + g + 8) * 100 + kb + tig * 2];
            a[2] = *(const unsigned*)&Qs[(mw + g)     * 100 + kb + 8 + tig * 2];
            a[3] = *(const unsigned*)&Qs[(mw + g + 8) * 100 + kb + 8 + tig * 2];
            #pragma unroll
            for (int nt = 0; nt < 4; nt++) {
                unsigned b[2];
                int c0 = nw2 + nt * 8 + g;
                b[0] = *(const unsigned*)&Ks[c0 * 100 + kb + tig * 2];
                b[1] = *(const unsigned*)&Ks[c0 * 100 + kb + 8 + tig * 2];
                mma16(sacc[nt], a, b);
            }
        }
        float m0 = -1e30f, m1 = -1e30f;
        #pragma unroll
        for (int nt = 0; nt < 4; nt++) {
            m0 = fmaxf(m0, fmaxf(sacc[nt][0], sacc[nt][1]));
            m1 = fmaxf(m1, fmaxf(sacc[nt][2], sacc[nt][3]));
        }
        m0 = fmaxf(m0, __shfl_xor_sync(~0u, m0, 1));
        m0 = fmaxf(m0, __shfl_xor_sync(~0u, m0, 2));
        m1 = fmaxf(m1, __shfl_xor_sync(~0u, m1, 1));
        m1 = fmaxf(m1, __shfl_xor_sync(~0u, m1, 2));
        float e[4][4];
        float s0 = 0.f, s1 = 0.f;
        #pragma unroll
        for (int nt = 0; nt < 4; nt++) {
            e[nt][0] = __expf(sacc[nt][0] - m0);
            e[nt][1] = __expf(sacc[nt][1] - m0);
            e[nt][2] = __expf(sacc[nt][2] - m1);
            e[nt][3] = __expf(sacc[nt][3] - m1);
            s0 += e[nt][0] + e[nt][1];
            s1 += e[nt][2] + e[nt][3];
        }
        s0 += __shfl_xor_sync(~0u, s0, 1); s0 += __shfl_xor_sync(~0u, s0, 2);
        s1 += __shfl_xor_sync(~0u, s1, 1); s1 += __shfl_xor_sync(~0u, s1, 2);
        if (tig == 0) {
            *(float2*)&Xc[(wh * 64 + mw + g) * 2]     = make_float2(m0, s0);
            *(float2*)&Xc[(wh * 64 + mw + g + 8) * 2] = make_float2(m1, s1);
        }
        __syncthreads();
        float2 o0 = *(float2*)&Xc[((1 ^ wh) * 64 + mw + g) * 2];
        float2 o1 = *(float2*)&Xc[((1 ^ wh) * 64 + mw + g + 8) * 2];
        float M0 = fmaxf(m0, o0.x);
        float sc0 = __expf(m0 - M0) / (s0 * __expf(m0 - M0) + o0.y * __expf(o0.x - M0));
        float M1 = fmaxf(m1, o1.x);
        float sc1 = __expf(m1 - M1) / (s1 * __expf(m1 - M1) + o1.y * __expf(o1.x - M1));
        {
            float* ao = attn_out + (size_t)((w * 3 + h) * 64) * 64;
            #pragma unroll
            for (int nt = 0; nt < 4; nt++) {
                int c = nw2 + nt * 8 + tig * 2;
                float p00 = e[nt][0] * sc0, p01 = e[nt][1] * sc0;
                float p10 = e[nt][2] * sc1, p11 = e[nt][3] * sc1;
                *(__nv_bfloat162*)&Ps[(mw + g) * 72 + c]     = __floats2bfloat162_rn(p00, p01);
                *(__nv_bfloat162*)&Ps[(mw + g + 8) * 72 + c] = __floats2bfloat162_rn(p10, p11);
                *(float2*)&ao[(size_t)(mw + g) * 64 + c]     = make_float2(p00, p01);
                *(float2*)&ao[(size_t)(mw + g + 8) * 64 + c] = make_float2(p10, p11);
            }
        }
        __syncthreads();

        // O = P @ V ; Os += (RMW onto lepe-init)
        {
            int d0 = h32 + wh * 16;
            float pacc[2][4] = {};
            #pragma unroll
            for (int ks = 0; ks < 4; ks++) {
                int kb = ks * 16;
                unsigned a[4];
                a[0] = *(const unsigned*)&Ps[(mw + g)     * 72 + kb + tig * 2];
                a[1] = *(const unsigned*)&Ps[(mw + g + 8) * 72 + kb + tig * 2];
                a[2] = *(const unsigned*)&Ps[(mw + g)     * 72 + kb + 8 + tig * 2];
                a[3] = *(const unsigned*)&Ps[(mw + g + 8) * 72 + kb + 8 + tig * 2];
                #pragma unroll
                for (int nt = 0; nt < 2; nt++) {
                    unsigned b[2];
                    int c0 = d0 + nt * 8 + g;
                    b[0] = *(const unsigned*)&Vt[c0 * 72 + kb + tig * 2];
                    b[1] = *(const unsigned*)&Vt[c0 * 72 + kb + 8 + tig * 2];
                    mma16(pacc[nt], a, b);
                }
            }
            #pragma unroll
            for (int nt = 0; nt < 2; nt++) {
                #pragma unroll
                for (int half = 0; half < 2; half++) {
                    int t = mw + g + half * 8;
                    #pragma unroll
                    for (int ee = 0; ee < 2; ee++) {
                        int d = d0 + nt * 8 + tig * 2 + ee;
                        float prev = __bfloat162float(Os[t * 100 + d]);
                        Os[t * 100 + d] =
                            __float2bfloat16(prev + pacc[nt][half * 2 + ee]);
                    }
                }
            }
        }
        __syncthreads();
    }

    // ---- phase 3: proj + residual(x from gmem) -> x1 staged in out gmem ----
    {
        int nw = wh * 48;
        float acc[6][4] = {};
        #pragma unroll
        for (int ks = 0; ks < 6; ks++) {
            int kb = ks * 16;
            unsigned a[4];
            a[0] = *(const unsigned*)&Os[(mw + g)     * 100 + kb + tig * 2];
            a[1] = *(const unsigned*)&Os[(mw + g + 8) * 100 + kb + tig * 2];
            a[2] = *(const unsigned*)&Os[(mw + g)     * 100 + kb + 8 + tig * 2];
            a[3] = *(const unsigned*)&Os[(mw + g + 8) * 100 + kb + 8 + tig * 2];
            #pragma unroll
            for (int nt = 0; nt < 6; nt++) {
                int n8 = wh * 6 + nt;
                uint2 v = __ldg(&g_wproj_p[(n8 * 6 + ks) * 32 + lane]);
                mma16(acc[nt], a, (const unsigned*)&v);
            }
        }
        #pragma unroll
        for (int half = 0; half < 2; half++) {
            int t = mw + g + half * 8;
            int tok = win2tok(w * 64 + t);
            #pragma unroll
            for (int nt = 0; nt < 6; nt++) {
                int c = nw + nt * 8 + tig * 2;
                float2 xr = __ldg((const float2*)&x[(size_t)tok * 96 + c]);
                float v0 = acc[nt][half * 2 + 0] + bproj[c]     + xr.x;
                float v1 = acc[nt][half * 2 + 1] + bproj[c + 1] + xr.y;
                *(float2*)(out + (size_t)tok * 96 + c) = make_float2(v0, v1);
            }
        }
    }
    __syncthreads();

    // ---- phase 4a: LN2 (x1 rows from out gmem) -> As ----
    #pragma unroll
    for (int r = 0; r < 8; r++) {
        int t = wid * 8 + r;
        const float* xr = out + (size_t)win2tok(w * 64 + t) * 96;
        float v0 = xr[lane], v1 = xr[lane + 32], v2 = xr[lane + 64];
        float s = v0 + v1 + v2;
        #pragma unroll
        for (int o = 16; o; o >>= 1) s += __shfl_xor_sync(~0u, s, o);
        float m = s * (1.f / 96.f);
        float d0 = v0 - m, d1 = v1 - m, d2 = v2 - m;
        float q = d0 * d0 + d1 * d1 + d2 * d2;
        #pragma unroll
        for (int o = 16; o; o >>= 1) q += __shfl_xor_sync(~0u, q, o);
        float rr = rsqrtf(q * (1.f / 96.f) + 1e-5f);
        As[t * 100 + lane]      = __float2bfloat16(d0 * rr * g2[lane]      + bt2[lane]);
        As[t * 100 + lane + 32] = __float2bfloat16(d1 * rr * g2[lane + 32] + bt2[lane + 32]);
        As[t * 100 + lane + 64] = __float2bfloat16(d2 * rr * g2[lane + 64] + bt2[lane + 64]);
    }
    __syncthreads();

    // ---- phase 4b: MLP chunks ----
    float acc2[6][4] = {};
    int nw = wh * 48;
    for (int c = 0; c < 4; c++) {
        float accH[6][4] = {};
        #pragma unroll
        for (int ks = 0; ks < 6; ks++) {
            int kb = ks * 16;
            unsigned a[4];
            a[0] = *(const unsigned*)&As[(mw + g)     * 100 + kb + tig * 2];
            a[1] = *(const unsigned*)&As[(mw + g + 8) * 100 + kb + tig * 2];
            a[2] = *(const unsigned*)&As[(mw + g)     * 100 + kb + 8 + tig * 2];
            a[3] = *(const unsigned*)&As[(mw + g + 8) * 100 + kb + 8 + tig * 2];
            #pragma unroll
            for (int nt = 0; nt < 6; nt++) {
                int n8 = c * 12 + wh * 6 + nt;
                uint2 v = __ldg(&g_w1_p[(n8 * 6 + ks) * 32 + lane]);
                mma16(accH[nt], a, (const unsigned*)&v);
            }
        }
        #pragma unroll
        for (int half = 0; half < 2; half++) {
            int row = mw + g + half * 8;
            #pragma unroll
            for (int nt = 0; nt < 6; nt++) {
                int col = nw + nt * 8 + tig * 2;
                float v0 = accH[nt][half * 2 + 0] + b1[c * 96 + col];
                float v1 = accH[nt][half * 2 + 1] + b1[c * 96 + col + 1];
                v0 = 0.5f * v0 * (1.f + erff(v0 * 0.70710678118f));
                v1 = 0.5f * v1 * (1.f + erff(v1 * 0.70710678118f));
                *(__nv_bfloat162*)&Hs[row * 100 + col] = __floats2bfloat162_rn(v0, v1);
            }
        }
        __syncthreads();

        #pragma unroll
        for (int ks = 0; ks < 6; ks++) {
            int kb = ks * 16;
            unsigned a[4];
            a[0] = *(const unsigned*)&Hs[(mw + g)     * 100 + kb + tig * 2];
            a[1] = *(const unsigned*)&Hs[(mw + g + 8) * 100 + kb + tig * 2];
            a[2] = *(const unsigned*)&Hs[(mw + g)     * 100 + kb + 8 + tig * 2];
            a[3] = *(const unsigned*)&Hs[(mw + g + 8) * 100 + kb + 8 + tig * 2];
            #pragma unroll
            for (int nt = 0; nt < 6; nt++) {
                int n8 = wh * 6 + nt;
                uint2 v = __ldg(&g_w2_p[c * 2304 + (n8 * 6 + ks) * 32 + lane]);
                mma16(acc2[nt], a, (const unsigned*)&v);
            }
        }
        __syncthreads();
    }

    // epilogue: out = x1(out gmem) + mlp + b2
    #pragma unroll
    for (int half = 0; half < 2; half++) {
        int t = mw + g + half * 8;
        int tok = win2tok(w * 64 + t);
        #pragma unroll
        for (int nt = 0; nt < 6; nt++) {
            int c = nw + nt * 8 + tig * 2;
            float2 x1r = __ldg((const float2*)&out[(size_t)tok * 96 + c]);
            float v0 = acc2[nt][half * 2 + 0] + b2[c]     + x1r.x;
            float v1 = acc2[nt][half * 2 + 1] + b2[c + 1] + x1r.y;
            *(float2*)(out + (size_t)tok * 96 + c) = make_float2(v0, v1);
        }
    }
}

// ---------------- launch ----------------
extern "C" void kernel_launch(void* const* d_in, const int* in_sizes, int n_in,
                              void* d_out, int out_size) {
    const float* x      = (const float*)d_in[0];
    const float* w_qkv  = (const float*)d_in[1];
    const float* b_qkv  = (const float*)d_in[2];
    const float* w_lepe = (const float*)d_in[3];
    const float* b_lepe = (const float*)d_in[4];
    const float* w_proj = (const float*)d_in[5];
    const float* b_proj = (const float*)d_in[6];
    const float* g1     = (const float*)d_in[7];
    const float* bt1    = (const float*)d_in[8];
    const float* g2     = (const float*)d_in[9];
    const float* bt2    = (const float*)d_in[10];
    const float* w_fc1  = (const float*)d_in[11];
    const float* b_fc1  = (const float*)d_in[12];
    const float* w_fc2  = (const float*)d_in[13];
    const float* b_fc2  = (const float*)d_in[14];

    float* out0 = (float*)d_out;

    float* pfb;
    cudaGetSymbolAddress((void**)&pfb, g_attn_fb);

    float* attn_out = (out_size >= OUT0_ELEMS + ATTN_ELEMS)
                        ? (out0 + OUT0_ELEMS) : pfb;

    cudaFuncSetAttribute(block_kernel,
                         cudaFuncAttributeMaxDynamicSharedMemorySize, SM_TOT);

    // 0. pack weights into mma b-fragment order
    prep_weights<<<108, 256>>>(w_qkv, w_proj, w_fc1, w_fc2);

    // 1. fully fused transformer block, one window per block
    block_kernel<<<NW_N, 256, SM_TOT>>>(x, b_qkv, w_lepe, b_lepe, b_proj,
                                        g1, bt1, g2, bt2, b_fc1, b_fc2,
                                        out0, attn_out);
}